// round 16
// baseline (speedup 1.0000x reference)
#include <cuda_runtime.h>
#include <cuda_bf16.h>
#include <mma.h>
#include <math.h>
#include <stdint.h>

using namespace nvcuda;

#define BBATCH 256
#define LLEN   128
#define KNBR   6
#define FAD    39
#define FBD    10
#define DDIM   128
#define NRAD   3
#define NTS    2
#define NEGV   (-9e8f)

static const int M_ATOM = BBATCH * LLEN;          // 32768

// ---------------- scratch (device globals; no allocations) ----------------
__device__ __align__(256) float g_h    [32768 * 128];
__device__ __align__(256) float g_act  [32768 * 128];
__device__ __align__(256) float g_P    [32768 * 128];
__device__ __align__(256) float g_atomT[32768 * 128];
__device__ __align__(256) float g_bondT[32768 * 128];
__device__ __align__(256) float g_gi   [32768 * 384];
__device__ __align__(256) float g_gh   [32768 * 384];
__device__ __align__(256) float g_sc   [32768];
__device__ __align__(256) float g_sn   [32768];
__device__ __align__(256) float g_sumw [32768];
__device__ __align__(256) float g_molf [256 * 128];
__device__ __align__(256) float g_pred [256];
// bf16 hi/lo activations
__device__ __align__(256) __nv_bfloat16 g_A64h [32768 * 64];
__device__ __align__(256) __nv_bfloat16 g_A64l [32768 * 64];
__device__ __align__(256) __nv_bfloat16 g_B64h [32768 * 64];
__device__ __align__(256) __nv_bfloat16 g_B64l [32768 * 64];
__device__ __align__(256) __nv_bfloat16 g_hh   [32768 * 128];
__device__ __align__(256) __nv_bfloat16 g_hl   [32768 * 128];
__device__ __align__(256) __nv_bfloat16 g_acth [32768 * 128];
__device__ __align__(256) __nv_bfloat16 g_actl [32768 * 128];
__device__ __align__(256) __nv_bfloat16 g_ctxh [32768 * 128];
__device__ __align__(256) __nv_bfloat16 g_ctxl [32768 * 128];
__device__ __align__(256) __nv_bfloat16 g_Ph   [32768 * 128];
__device__ __align__(256) __nv_bfloat16 g_Pl   [32768 * 128];
// bf16 hi/lo weights
__device__ __align__(256) __nv_bfloat16 g_Wah [64 * 128];
__device__ __align__(256) __nv_bfloat16 g_Wal [64 * 128];
__device__ __align__(256) __nv_bfloat16 g_Wth [64 * 128];
__device__ __align__(256) __nv_bfloat16 g_Wtl [64 * 128];
__device__ __align__(256) __nv_bfloat16 g_Wbh [64 * 128];
__device__ __align__(256) __nv_bfloat16 g_Wbl [64 * 128];
__device__ __align__(256) __nv_bfloat16 g_AWh [4 * 128 * 128];
__device__ __align__(256) __nv_bfloat16 g_AWl [4 * 128 * 128];
__device__ __align__(256) __nv_bfloat16 g_WIHh[3 * 384 * 128];
__device__ __align__(256) __nv_bfloat16 g_WIHl[3 * 384 * 128];
__device__ __align__(256) __nv_bfloat16 g_WHHh[3 * 384 * 128];
__device__ __align__(256) __nv_bfloat16 g_WHHl[3 * 384 * 128];

// ---------------- helpers ----------------
__device__ __forceinline__ void f2bf_split(float x, __nv_bfloat16& hi, __nv_bfloat16& lo)
{
    hi = __float2bfloat16(x);
    lo = __float2bfloat16(x - __bfloat162float(hi));
}
__device__ __forceinline__ void f2bf_split2(float x, float y,
                                            __nv_bfloat162& hi, __nv_bfloat162& lo)
{
    __nv_bfloat16 hx = __float2bfloat16(x);
    __nv_bfloat16 hy = __float2bfloat16(y);
    hi = __nv_bfloat162(hx, hy);
    lo = __nv_bfloat162(__float2bfloat16(x - __bfloat162float(hx)),
                        __float2bfloat16(y - __bfloat162float(hy)));
}
__device__ __forceinline__ void store_split4(__nv_bfloat16* dh, __nv_bfloat16* dl,
                                             size_t off, float4 v)
{
    __nv_bfloat162 h0, l0, h1, l1;
    f2bf_split2(v.x, v.y, h0, l0);
    f2bf_split2(v.z, v.w, h1, l1);
    *(__nv_bfloat162*)(dh + off)     = h0;
    *(__nv_bfloat162*)(dh + off + 2) = h1;
    *(__nv_bfloat162*)(dl + off)     = l0;
    *(__nv_bfloat162*)(dl + off + 2) = l1;
}
__device__ __forceinline__ float warp_bsum(float v)
{
#pragma unroll
    for (int o = 16; o > 0; o >>= 1) v += __shfl_xor_sync(0xffffffffu, v, o);
    return v;
}
__device__ __forceinline__ uint32_t smem_u32(const void* p)
{
    uint32_t a;
    asm("{ .reg .u64 t; cvta.to.shared.u64 t, %1; cvt.u32.u64 %0, t; }" : "=r"(a) : "l"(p));
    return a;
}
__device__ __forceinline__ void cp16(uint32_t dst, const void* src)
{
    asm volatile("cp.async.ca.shared.global [%0], [%1], 16;" :: "r"(dst), "l"(src));
}
__device__ __forceinline__ void cp_commit() { asm volatile("cp.async.commit_group;"); }
__device__ __forceinline__ void cp_wait1()  { asm volatile("cp.async.wait_group 1;"); }
__device__ __forceinline__ void cp_wait0()  { asm volatile("cp.async.wait_group 0;"); }

// ============== bf16x3 GEMM body, BK=64, cp.async 2-stage pipeline =========
template<int BL, int MODE, int OUT>
__device__ __forceinline__ void gemm_body(
    const __nv_bfloat16* __restrict__ Ah, const __nv_bfloat16* __restrict__ Al,
    const __nv_bfloat16* __restrict__ Bh, const __nv_bfloat16* __restrict__ Bl,
    const float* __restrict__ bias, const float* __restrict__ rowscale,
    float* __restrict__ C, __nv_bfloat16* __restrict__ Chi, __nv_bfloat16* __restrict__ Clo,
    int K, int N, char* dyn)
{
    constexpr int LDA = 72;
    constexpr int LDB = 72;
    constexpr int A_SZ = 128 * LDA;
    constexpr int B_SZ = 64 * LDB;
    constexpr int STG  = 2 * A_SZ + 2 * B_SZ;

    __nv_bfloat16* base = (__nv_bfloat16*)dyn;
    const uint32_t sbase = smem_u32(dyn);
    const int tid  = threadIdx.x;
    const int warp = tid >> 5;
    const int wm = warp >> 1, wn = warp & 1;
    const int m0 = blockIdx.x * 128, n0 = blockIdx.y * 64;

    auto issue = [&](int kt, int s) {
        const int k0 = kt << 6;
        const uint32_t su = sbase + (uint32_t)s * STG * 2;
#pragma unroll
        for (int t = 0; t < 4; ++t) {
            int i = tid + t * 256;
            int row = i >> 3, q = (i & 7) * 8;
            size_t goff = (size_t)(m0 + row) * K + k0 + q;
            cp16(su + (row * LDA + q) * 2,          Ah + goff);
            cp16(su + (A_SZ + row * LDA + q) * 2,   Al + goff);
        }
#pragma unroll
        for (int t = 0; t < 2; ++t) {
            int i = tid + t * 256;
            int r = i >> 3, q = (i & 7) * 8;
            size_t goff;
            if (BL == 0) goff = (size_t)(k0 + r) * N + n0 + q;
            else         goff = (size_t)(n0 + r) * K + k0 + q;
            cp16(su + (2 * A_SZ + r * LDB + q) * 2,        Bh + goff);
            cp16(su + (2 * A_SZ + B_SZ + r * LDB + q) * 2, Bl + goff);
        }
        cp_commit();
    };

    wmma::fragment<wmma::accumulator, 16, 16, 16, float> acc[2][2];
#pragma unroll
    for (int mi = 0; mi < 2; ++mi)
#pragma unroll
        for (int ni = 0; ni < 2; ++ni) wmma::fill_fragment(acc[mi][ni], 0.f);

    const int nk = K >> 6;
    issue(0, 0);
    for (int kt = 0; kt < nk; ++kt) {
        if (kt + 1 < nk) { issue(kt + 1, (kt + 1) & 1); cp_wait1(); }
        else             { cp_wait0(); }
        __syncthreads();
        const __nv_bfloat16* st  = base + (size_t)(kt & 1) * STG;
        const __nv_bfloat16* sAh = st;
        const __nv_bfloat16* sAl = st + A_SZ;
        const __nv_bfloat16* sBh = st + 2 * A_SZ;
        const __nv_bfloat16* sBl = sBh + B_SZ;
#pragma unroll
        for (int kc = 0; kc < 64; kc += 16) {
            wmma::fragment<wmma::matrix_a, 16, 16, 16, __nv_bfloat16, wmma::row_major> ah[2], al[2];
#pragma unroll
            for (int mi = 0; mi < 2; ++mi) {
                wmma::load_matrix_sync(ah[mi], sAh + (wm * 32 + mi * 16) * LDA + kc, LDA);
                wmma::load_matrix_sync(al[mi], sAl + (wm * 32 + mi * 16) * LDA + kc, LDA);
            }
            if (BL == 0) {
                wmma::fragment<wmma::matrix_b, 16, 16, 16, __nv_bfloat16, wmma::row_major> bh[2], bl[2];
#pragma unroll
                for (int ni = 0; ni < 2; ++ni) {
                    wmma::load_matrix_sync(bh[ni], sBh + kc * LDB + wn * 32 + ni * 16, LDB);
                    wmma::load_matrix_sync(bl[ni], sBl + kc * LDB + wn * 32 + ni * 16, LDB);
                }
#pragma unroll
                for (int mi = 0; mi < 2; ++mi)
#pragma unroll
                    for (int ni = 0; ni < 2; ++ni) {
                        wmma::mma_sync(acc[mi][ni], ah[mi], bl[ni], acc[mi][ni]);
                        wmma::mma_sync(acc[mi][ni], al[mi], bh[ni], acc[mi][ni]);
                        wmma::mma_sync(acc[mi][ni], ah[mi], bh[ni], acc[mi][ni]);
                    }
            } else {
                wmma::fragment<wmma::matrix_b, 16, 16, 16, __nv_bfloat16, wmma::col_major> bh[2], bl[2];
#pragma unroll
                for (int ni = 0; ni < 2; ++ni) {
                    wmma::load_matrix_sync(bh[ni], sBh + (wn * 32 + ni * 16) * LDB + kc, LDB);
                    wmma::load_matrix_sync(bl[ni], sBl + (wn * 32 + ni * 16) * LDB + kc, LDB);
                }
#pragma unroll
                for (int mi = 0; mi < 2; ++mi)
#pragma unroll
                    for (int ni = 0; ni < 2; ++ni) {
                        wmma::mma_sync(acc[mi][ni], ah[mi], bl[ni], acc[mi][ni]);
                        wmma::mma_sync(acc[mi][ni], al[mi], bh[ni], acc[mi][ni]);
                        wmma::mma_sync(acc[mi][ni], ah[mi], bh[ni], acc[mi][ni]);
                    }
            }
        }
        __syncthreads();
    }
    float* Cs = (float*)dyn;
#pragma unroll
    for (int mi = 0; mi < 2; ++mi)
#pragma unroll
        for (int ni = 0; ni < 2; ++ni)
            wmma::store_matrix_sync(Cs + (wm * 32 + mi * 16) * 72 + (wn * 32 + ni * 16),
                                    acc[mi][ni], 72, wmma::mem_row_major);
    __syncthreads();
#pragma unroll
    for (int t = 0; t < 8; ++t) {
        int i = tid + t * 256;
        int row = i >> 4, c4 = i & 15;
        float4 v = *(float4*)(Cs + row * 72 + c4 * 4);
        int n = n0 + c4 * 4;
        if (MODE == 1) {
            v.x += bias[n];     v.y += bias[n + 1];  v.z += bias[n + 2];  v.w += bias[n + 3];
            v.x = v.x > 0.f ? v.x : 0.01f * v.x;
            v.y = v.y > 0.f ? v.y : 0.01f * v.y;
            v.z = v.z > 0.f ? v.z : 0.01f * v.z;
            v.w = v.w > 0.f ? v.w : 0.01f * v.w;
        } else if (MODE == 3) {
            float rs = rowscale[m0 + row];
            v.x += rs * bias[n];     v.y += rs * bias[n + 1];
            v.z += rs * bias[n + 2]; v.w += rs * bias[n + 3];
            v.x = v.x > 0.f ? v.x : expm1f(v.x);
            v.y = v.y > 0.f ? v.y : expm1f(v.y);
            v.z = v.z > 0.f ? v.z : expm1f(v.z);
            v.w = v.w > 0.f ? v.w : expm1f(v.w);
        }
        size_t off = (size_t)(m0 + row) * N + n;
        if (OUT & 1) *(float4*)(C + off) = v;
        if (OUT & 2) store_split4(Chi, Clo, off, v);
    }
}

template<int BL, int MODE, int OUT>
__global__ void __launch_bounds__(256) gemm_bf_k(
    const __nv_bfloat16* __restrict__ Ah, const __nv_bfloat16* __restrict__ Al,
    const __nv_bfloat16* __restrict__ Bh, const __nv_bfloat16* __restrict__ Bl,
    const float* __restrict__ bias, const float* __restrict__ rowscale,
    float* __restrict__ C, __nv_bfloat16* __restrict__ Chi, __nv_bfloat16* __restrict__ Clo,
    int K, int N)
{
    extern __shared__ __align__(16) char dyn[];
    gemm_body<BL, MODE, OUT>(Ah, Al, Bh, Bl, bias, rowscale, C, Chi, Clo, K, N, dyn);
}

// merged GRU GEMM: z=0 -> gi = ctx@WIH^T, z=1 -> gh = h@WHH^T
__global__ void __launch_bounds__(256) gemm_gru_k(
    const __nv_bfloat16* __restrict__ ctxh, const __nv_bfloat16* __restrict__ ctxl,
    const __nv_bfloat16* __restrict__ hh,   const __nv_bfloat16* __restrict__ hl,
    const __nv_bfloat16* __restrict__ WIHh, const __nv_bfloat16* __restrict__ WIHl,
    const __nv_bfloat16* __restrict__ WHHh, const __nv_bfloat16* __restrict__ WHHl,
    float* __restrict__ gi, float* __restrict__ gh)
{
    extern __shared__ __align__(16) char dyn[];
    if (blockIdx.z == 0)
        gemm_body<1, 0, 1>(ctxh, ctxl, WIHh, WIHl, nullptr, nullptr,
                           gi, nullptr, nullptr, DDIM, 384, dyn);
    else
        gemm_body<1, 0, 1>(hh, hl, WHHh, WHHl, nullptr, nullptr,
                           gh, nullptr, nullptr, DDIM, 384, dyn);
}

// ---------------- block reductions (mol_k only) ----------------
__device__ __forceinline__ float blk_sum(float v, float* red, int j)
{
#pragma unroll
    for (int o = 16; o > 0; o >>= 1) v += __shfl_down_sync(0xffffffffu, v, o);
    if ((j & 31) == 0) red[j >> 5] = v;
    __syncthreads();
    v = red[0] + red[1] + red[2] + red[3];
    __syncthreads();
    return v;
}
__device__ __forceinline__ float blk_max(float v, float* red, int j)
{
#pragma unroll
    for (int o = 16; o > 0; o >>= 1) v = fmaxf(v, __shfl_down_sync(0xffffffffu, v, o));
    if ((j & 31) == 0) red[j >> 5] = v;
    __syncthreads();
    v = fmaxf(fmaxf(red[0], red[1]), fmaxf(red[2], red[3]));
    __syncthreads();
    return v;
}

// ============== ONE merged conversion kernel ====
#define N_S0 2097152
#define N_S1 2097152
#define N_S2 8192
#define N_S3 8192
#define N_S4 8192
#define N_S5 65536
#define N_S6 147456
#define CONV_TOTAL (N_S0 + N_S1 + N_S2 + N_S3 + N_S4 + N_S5 + 2 * N_S6)

__global__ void conv_all_k(
    const float* __restrict__ atom, const float* __restrict__ bond,
    const float* __restrict__ atom_fc_w, const float* __restrict__ nbr_fc_w,
    const float* __restrict__ attend_w, const float* __restrict__ mol_attend_w,
    const float* __restrict__ gru_wih, const float* __restrict__ gru_whh,
    __nv_bfloat16* __restrict__ A64h, __nv_bfloat16* __restrict__ A64l,
    __nv_bfloat16* __restrict__ B64h, __nv_bfloat16* __restrict__ B64l,
    __nv_bfloat16* __restrict__ Wah,  __nv_bfloat16* __restrict__ Wal,
    __nv_bfloat16* __restrict__ Wth,  __nv_bfloat16* __restrict__ Wtl,
    __nv_bfloat16* __restrict__ Wbh,  __nv_bfloat16* __restrict__ Wbl,
    __nv_bfloat16* __restrict__ AWh,  __nv_bfloat16* __restrict__ AWl,
    __nv_bfloat16* __restrict__ WIHh, __nv_bfloat16* __restrict__ WIHl,
    __nv_bfloat16* __restrict__ WHHh, __nv_bfloat16* __restrict__ WHHl)
{
    int i = blockIdx.x * blockDim.x + threadIdx.x;
    if (i >= CONV_TOTAL) return;
    float v; __nv_bfloat16 h, l;
    if (i < N_S0) {
        int r = i >> 6, t = i & 63;
        v = (t < FAD) ? atom[(size_t)r * FAD + t] : 0.f;
        f2bf_split(v, h, l); A64h[i] = h; A64l[i] = l; return;
    }
    i -= N_S0;
    if (i < N_S1) {
        int r = i >> 6, t = i & 63;
        v = (t < FBD) ? bond[(size_t)r * FBD + t] : 0.f;
        f2bf_split(v, h, l); B64h[i] = h; B64l[i] = l; return;
    }
    i -= N_S1;
    if (i < N_S2) {
        int r = i >> 7;
        v = (r < FAD) ? atom_fc_w[i] : 0.f;
        f2bf_split(v, h, l); Wah[i] = h; Wal[i] = l; return;
    }
    i -= N_S2;
    if (i < N_S3) {
        int r = i >> 7;
        v = (r < FAD) ? nbr_fc_w[i] : 0.f;
        f2bf_split(v, h, l); Wth[i] = h; Wtl[i] = l; return;
    }
    i -= N_S3;
    if (i < N_S4) {
        int r = i >> 7, j = i & 127;
        v = (r < FBD) ? nbr_fc_w[(FAD + r) * 128 + j] : 0.f;
        f2bf_split(v, h, l); Wbh[i] = h; Wbl[i] = l; return;
    }
    i -= N_S4;
    if (i < N_S5) {
        v = (i < 49152) ? attend_w[i] : mol_attend_w[i - 49152];
        f2bf_split(v, h, l); AWh[i] = h; AWl[i] = l; return;
    }
    i -= N_S5;
    if (i < N_S6) {
        v = gru_wih[i];
        f2bf_split(v, h, l); WIHh[i] = h; WIHl[i] = l; return;
    }
    i -= N_S6;
    v = gru_whh[i];
    f2bf_split(v, h, l); WHHh[i] = h; WHHl[i] = l;
}

// ---------------- fused d=0 attention: one WARP per atom ----------------
__global__ void __launch_bounds__(256) attn0_k(
    const float* __restrict__ h, const float* __restrict__ atomT,
    const float* __restrict__ bondT, const int* __restrict__ adl,
    const int* __restrict__ bdl, const float* __restrict__ nbias,
    const float* __restrict__ aw, const float* __restrict__ ab,
    __nv_bfloat16* __restrict__ ph, __nv_bfloat16* __restrict__ pl,
    float* __restrict__ sumw)
{
    int bl   = (blockIdx.x << 3) + (threadIdx.x >> 5);
    int lane = threadIdx.x & 31;
    int j    = lane * 4;
    int bbase = (bl >> 7) << 7;
    const int base = bl * KNBR;

    float4 hx  = *(const float4*)(h + (size_t)bl * DDIM + j);
    float4 a1  = *(const float4*)(aw + j);
    float sc = warp_bsum(hx.x * a1.x + hx.y * a1.y + hx.z * a1.z + hx.w * a1.w);
    float4 a2  = *(const float4*)(aw + DDIM + j);
    float4 nb  = *(const float4*)(nbias + j);
    float ab0 = ab[0];

    float4 v[KNBR];
    float s[KNBR], msk[KNBR];
#pragma unroll
    for (int k = 0; k < KNBR; ++k) {
        int ai = adl[base + k], bi = bdl[base + k];
        float4 av = *(const float4*)(atomT + (size_t)(bbase + ai) * DDIM + j);
        float4 bv = *(const float4*)(bondT + (size_t)(bbase + bi) * DDIM + j);
        float4 x;
        x.x = av.x + bv.x + nb.x; x.x = x.x > 0.f ? x.x : 0.01f * x.x;
        x.y = av.y + bv.y + nb.y; x.y = x.y > 0.f ? x.y : 0.01f * x.y;
        x.z = av.z + bv.z + nb.z; x.z = x.z > 0.f ? x.z : 0.01f * x.z;
        x.w = av.w + bv.w + nb.w; x.w = x.w > 0.f ? x.w : 0.01f * x.w;
        v[k] = x;
        msk[k] = (ai == LLEN - 1) ? 0.f : 1.f;
        float d = warp_bsum(x.x * a2.x + x.y * a2.y + x.z * a2.z + x.w * a2.w);
        float sco = sc + d + ab0;
        sco = sco > 0.f ? sco : 0.01f * sco;
        if (msk[k] == 0.f) sco += NEGV;
        s[k] = sco;
    }
    float mx = -1e30f;
#pragma unroll
    for (int k = 0; k < KNBR; ++k) mx = fmaxf(mx, s[k]);
    float ss = 0.f;
#pragma unroll
    for (int k = 0; k < KNBR; ++k) { s[k] = expf(s[k] - mx); ss += s[k]; }
    float4 acc = make_float4(0.f, 0.f, 0.f, 0.f);
    float sw = 0.f;
#pragma unroll
    for (int k = 0; k < KNBR; ++k) {
        float w = s[k] / ss * msk[k];
        acc.x = fmaf(w, v[k].x, acc.x);
        acc.y = fmaf(w, v[k].y, acc.y);
        acc.z = fmaf(w, v[k].z, acc.z);
        acc.w = fmaf(w, v[k].w, acc.w);
        sw += w;
    }
    store_split4(ph, pl, (size_t)bl * DDIM + j, acc);
    if (lane == 0) sumw[bl] = sw;
}

// ---------------- warp-per-row dot kernels ----------------
__global__ void __launch_bounds__(256) dot2_k(
    const float* __restrict__ X, const float* __restrict__ w1,
    const float* __restrict__ w2, float* __restrict__ o1, float* __restrict__ o2)
{
    int warp = (blockIdx.x << 3) + (threadIdx.x >> 5);
    int lane = threadIdx.x & 31;
    const float4 x  = *(const float4*)(X + (size_t)warp * DDIM + lane * 4);
    const float4 a4 = *(const float4*)(w1 + lane * 4);
    const float4 b4 = *(const float4*)(w2 + lane * 4);
    float a = x.x * a4.x + x.y * a4.y + x.z * a4.z + x.w * a4.w;
    float b = x.x * b4.x + x.y * b4.y + x.z * b4.z + x.w * b4.w;
#pragma unroll
    for (int o = 16; o > 0; o >>= 1) {
        a += __shfl_down_sync(0xffffffffu, a, o);
        b += __shfl_down_sync(0xffffffffu, b, o);
    }
    if (lane == 0) { o1[warp] = a; o2[warp] = b; }
}
__global__ void __launch_bounds__(256) dot128_k(
    const float* __restrict__ X, const float* __restrict__ v, float* __restrict__ out)
{
    int warp = (blockIdx.x << 3) + (threadIdx.x >> 5);
    int lane = threadIdx.x & 31;
    const float4 x  = *(const float4*)(X + (size_t)warp * DDIM + lane * 4);
    const float4 a4 = *(const float4*)(v + lane * 4);
    float a = x.x * a4.x + x.y * a4.y + x.z * a4.z + x.w * a4.w;
#pragma unroll
    for (int o = 16; o > 0; o >>= 1) a += __shfl_down_sync(0xffffffffu, a, o);
    if (lane == 0) out[warp] = a;
}

// ---------------- d>=1 attention: one WARP per atom ----------------
__global__ void __launch_bounds__(256) attn_k(
    const float* __restrict__ sc, const float* __restrict__ sn,
    const float* __restrict__ P, const int* __restrict__ adl,
    const float* __restrict__ abp, const float* __restrict__ tb,
    __nv_bfloat16* __restrict__ ctxh, __nv_bfloat16* __restrict__ ctxl)
{
    int bl   = (blockIdx.x << 3) + (threadIdx.x >> 5);
    int lane = threadIdx.x & 31;
    int j    = lane * 4;
    int b    = bl >> 7;
    float ab  = abp[0];
    float scv = sc[bl];

    int src[KNBR];
    float s[KNBR], msk[KNBR];
    float mx = -1e30f;
#pragma unroll
    for (int k = 0; k < KNBR; ++k) {
        int id = adl[bl * KNBR + k];
        src[k] = b * LLEN + id;
        float sco = scv + sn[src[k]] + ab;
        sco = sco > 0.f ? sco : 0.01f * sco;
        bool pad = (id == LLEN - 1);
        if (pad) sco += NEGV;
        msk[k] = pad ? 0.f : 1.f;
        s[k] = sco;
        mx = fmaxf(mx, sco);
    }
    float sum = 0.f;
#pragma unroll
    for (int k = 0; k < KNBR; ++k) { s[k] = expf(s[k] - mx); sum += s[k]; }
    float sw = 0.f;
    float4 c = make_float4(0.f, 0.f, 0.f, 0.f);
#pragma unroll
    for (int k = 0; k < KNBR; ++k) {
        float w = s[k] / sum * msk[k];
        sw += w;
        float4 p4 = *(const float4*)(P + (size_t)src[k] * DDIM + j);
        c.x = fmaf(w, p4.x, c.x);
        c.y = fmaf(w, p4.y, c.y);
        c.z = fmaf(w, p4.z, c.z);
        c.w = fmaf(w, p4.w, c.w);
    }
    float4 t4 = *(const float4*)(tb + j);
    c.x += sw * t4.x; c.x = c.x > 0.f ? c.x : expm1f(c.x);
    c.y += sw * t4.y; c.y = c.y > 0.f ? c.y : expm1f(c.y);
    c.z += sw * t4.z; c.z = c.z > 0.f ? c.z : expm1f(c.z);
    c.w += sw * t4.w; c.w = c.w > 0.f ? c.w : expm1f(c.w);
    store_split4(ctxh, ctxl, (size_t)bl * DDIM + j, c);
}

// ---------------- GRU gate fusion, float4-vectorized ----------------
__global__ void gru_gate_k(const float* __restrict__ gi, const float* __restrict__ gh,
                           const float* __restrict__ bih, const float* __restrict__ bhh,
                           float* __restrict__ h, float* __restrict__ act,
                           __nv_bfloat16* __restrict__ hh_o, __nv_bfloat16* __restrict__ hl_o,
                           __nv_bfloat16* __restrict__ ah_o, __nv_bfloat16* __restrict__ al_o,
                           float* __restrict__ out_h, int M)
{
    int g4 = blockIdx.x * blockDim.x + threadIdx.x;
    if (g4 >= M * 32) return;
    int m = g4 >> 5, j = (g4 & 31) * 4;
    size_t gbase = (size_t)m * 384 + j;
    size_t hbase = (size_t)m * 128 + j;
    float4 ir = *(const float4*)(gi + gbase);
    float4 iz = *(const float4*)(gi + gbase + 128);
    float4 in = *(const float4*)(gi + gbase + 256);
    float4 hr = *(const float4*)(gh + gbase);
    float4 hz = *(const float4*)(gh + gbase + 128);
    float4 hn = *(const float4*)(gh + gbase + 256);
    float4 b0 = *(const float4*)(bih + j);
    float4 b1 = *(const float4*)(bih + 128 + j);
    float4 b2 = *(const float4*)(bih + 256 + j);
    float4 c0 = *(const float4*)(bhh + j);
    float4 c1 = *(const float4*)(bhh + 128 + j);
    float4 c2 = *(const float4*)(bhh + 256 + j);
    float4 hv = *(const float4*)(h + hbase);
    float4 hnew, av;
#pragma unroll
    for (int e = 0; e < 4; ++e) {
        float irv = (&ir.x)[e] + (&b0.x)[e];
        float izv = (&iz.x)[e] + (&b1.x)[e];
        float inv = (&in.x)[e] + (&b2.x)[e];
        float hrv = (&hr.x)[e] + (&c0.x)[e];
        float hzv = (&hz.x)[e] + (&c1.x)[e];
        float hnv = (&hn.x)[e] + (&c2.x)[e];
        float r = 1.f / (1.f + expf(-(irv + hrv)));
        float z = 1.f / (1.f + expf(-(izv + hzv)));
        float n = tanhf(inv + r * hnv);
        float ho = (1.f - z) * n + z * (&hv.x)[e];
        (&hnew.x)[e] = ho;
        (&av.x)[e] = ho > 0.f ? ho : 0.f;
    }
    *(float4*)(h + hbase)   = hnew;
    *(float4*)(act + hbase) = av;
    store_split4(hh_o, hl_o, hbase, hnew);
    store_split4(ah_o, al_o, hbase, av);
    if (out_h) *(float4*)(out_h + hbase) = hnew;
}

// ---------------- masked sum over atoms ----------------
__global__ void molsum_k(const float* __restrict__ act, const float* __restrict__ mask,
                         float* __restrict__ molf)
{
    int b = blockIdx.x, j = threadIdx.x;
    float s = 0.f;
    for (int l = 0; l < LLEN; ++l)
        s = fmaf(act[((size_t)b * LLEN + l) * DDIM + j], mask[b * LLEN + l], s);
    molf[b * DDIM + j] = s;
}

// ---------------- per-molecule mol-attention + GRU ----------------
__global__ void mol_k(const float* __restrict__ molf_in, const float* __restrict__ mask,
                      const float* __restrict__ snm, const float* __restrict__ Pm,
                      const float* __restrict__ maw, const float* __restrict__ mab,
                      const float* __restrict__ matt_b,
                      const float* __restrict__ wih, const float* __restrict__ whh,
                      const float* __restrict__ bih, const float* __restrict__ bhh,
                      const float* __restrict__ outw, const float* __restrict__ outb,
                      float* __restrict__ molf_out, float* __restrict__ pred)
{
    int b = blockIdx.x;
    int j = threadIdx.x;
    __shared__ float smolf[DDIM];
    __shared__ float w[LLEN];
    __shared__ float sctx[DDIM];
    __shared__ float red[4];
    smolf[j] = molf_in[b * DDIM + j];
    float mymask = mask[b * LLEN + j];
    float mysnm  = snm[b * LLEN + j];
    float mabv   = mab[0];
    float mybias = matt_b[j];

    for (int t = 0; t < NTS; ++t) {
        __syncthreads();
        float amj = fmaxf(smolf[j], 0.f);
        float scv = blk_sum(amj * maw[j], red, j);
        float sco = scv + mysnm + mabv;
        sco = sco > 0.f ? sco : 0.01f * sco;
        if (mymask == 0.f) sco += NEGV;
        float mx = blk_max(sco, red, j);
        float ev = expf(sco - mx);
        float ss = blk_sum(ev, red, j);
        float wj = ev / ss * mymask;
        w[j] = wj;
        float sumw = blk_sum(wj, red, j);
        __syncthreads();
        float c = 0.f;
#pragma unroll 4
        for (int l = 0; l < LLEN; ++l)
            c = fmaf(w[l], Pm[((size_t)b * LLEN + l) * DDIM + j], c);
        c += sumw * mybias;
        c = c > 0.f ? c : expm1f(c);
        sctx[j] = c;
        __syncthreads();
        float gi0 = bih[j], gi1 = bih[DDIM + j], gi2 = bih[2 * DDIM + j];
        float gh0 = bhh[j], gh1 = bhh[DDIM + j], gh2 = bhh[2 * DDIM + j];
        const float* wi0 = wih + (size_t)j * DDIM;
        const float* wi1 = wih + (size_t)(DDIM + j) * DDIM;
        const float* wi2 = wih + (size_t)(2 * DDIM + j) * DDIM;
        const float* wh0 = whh + (size_t)j * DDIM;
        const float* wh1 = whh + (size_t)(DDIM + j) * DDIM;
        const float* wh2 = whh + (size_t)(2 * DDIM + j) * DDIM;
#pragma unroll 4
        for (int k = 0; k < DDIM; ++k) {
            float ck = sctx[k], hk = smolf[k];
            gi0 = fmaf(ck, wi0[k], gi0);
            gi1 = fmaf(ck, wi1[k], gi1);
            gi2 = fmaf(ck, wi2[k], gi2);
            gh0 = fmaf(hk, wh0[k], gh0);
            gh1 = fmaf(hk, wh1[k], gh1);
            gh2 = fmaf(hk, wh2[k], gh2);
        }
        float r = 1.f / (1.f + expf(-(gi0 + gh0)));
        float z = 1.f / (1.f + expf(-(gi1 + gh1)));
        float n = tanhf(gi2 + r * gh2);
        float hnew = (1.f - z) * n + z * smolf[j];
        __syncthreads();
        smolf[j] = hnew;
    }
    __syncthreads();
    molf_out[b * DDIM + j] = smolf[j];
    float tot = blk_sum(smolf[j] * outw[j], red, j);
    if (j == 0) pred[b] = tot + outb[0];
}

__global__ void copy_k(const float* __restrict__ src, float* __restrict__ dst, int n)
{
    int i = blockIdx.x * blockDim.x + threadIdx.x;
    if (i < n) dst[i] = src[i];
}

// ---------------- launcher ----------------
extern "C" void kernel_launch(void* const* d_in, const int* in_sizes, int n_in,
                              void* d_out, int out_size)
{
    const float* atom_list    = (const float*)d_in[0];
    const float* bond_list    = (const float*)d_in[1];
    const float* atom_mask    = (const float*)d_in[2];
    const float* atom_fc_w    = (const float*)d_in[3];
    const float* atom_fc_b    = (const float*)d_in[4];
    const float* nbr_fc_w     = (const float*)d_in[5];
    const float* nbr_fc_b     = (const float*)d_in[6];
    const float* align_w      = (const float*)d_in[7];
    const float* align_b      = (const float*)d_in[8];
    const float* attend_w     = (const float*)d_in[9];
    const float* attend_b     = (const float*)d_in[10];
    const float* gru_wih      = (const float*)d_in[11];
    const float* gru_whh      = (const float*)d_in[12];
    const float* gru_bih      = (const float*)d_in[13];
    const float* gru_bhh      = (const float*)d_in[14];
    const float* mol_align_w  = (const float*)d_in[15];
    const float* mol_align_b  = (const float*)d_in[16];
    const float* mol_attend_w = (const float*)d_in[17];
    const float* mol_attend_b = (const float*)d_in[18];
    const float* mol_gru_wih  = (const float*)d_in[19];
    const float* mol_gru_whh  = (const float*)d_in[20];
    const float* mol_gru_bih  = (const float*)d_in[21];
    const float* mol_gru_bhh  = (const float*)d_in[22];
    const float* out_w        = (const float*)d_in[23];
    const float* out_b        = (const float*)d_in[24];
    const int*   adl          = (const int*)d_in[25];
    const int*   bdl          = (const int*)d_in[26];

    float *p_h, *p_act, *p_P, *p_atomT, *p_bondT, *p_gi, *p_gh,
          *p_sc, *p_sn, *p_sumw, *p_molf, *p_pred;
    __nv_bfloat16 *A64h, *A64l, *B64h, *B64l, *hh, *hl, *acth, *actl,
                  *ctxh, *ctxl, *Ph, *Pl, *Wah, *Wal, *Wth, *Wtl, *Wbh, *Wbl,
                  *AWh, *AWl, *WIHh, *WIHl, *WHHh, *WHHl;
    cudaGetSymbolAddress((void**)&p_h,     g_h);
    cudaGetSymbolAddress((void**)&p_act,   g_act);
    cudaGetSymbolAddress((void**)&p_P,     g_P);
    cudaGetSymbolAddress((void**)&p_atomT, g_atomT);
    cudaGetSymbolAddress((void**)&p_bondT, g_bondT);
    cudaGetSymbolAddress((void**)&p_gi,    g_gi);
    cudaGetSymbolAddress((void**)&p_gh,    g_gh);
    cudaGetSymbolAddress((void**)&p_sc,    g_sc);
    cudaGetSymbolAddress((void**)&p_sn,    g_sn);
    cudaGetSymbolAddress((void**)&p_sumw,  g_sumw);
    cudaGetSymbolAddress((void**)&p_molf,  g_molf);
    cudaGetSymbolAddress((void**)&p_pred,  g_pred);
    cudaGetSymbolAddress((void**)&A64h, g_A64h);  cudaGetSymbolAddress((void**)&A64l, g_A64l);
    cudaGetSymbolAddress((void**)&B64h, g_B64h);  cudaGetSymbolAddress((void**)&B64l, g_B64l);
    cudaGetSymbolAddress((void**)&hh,   g_hh);    cudaGetSymbolAddress((void**)&hl,   g_hl);
    cudaGetSymbolAddress((void**)&acth, g_acth);  cudaGetSymbolAddress((void**)&actl, g_actl);
    cudaGetSymbolAddress((void**)&ctxh, g_ctxh);  cudaGetSymbolAddress((void**)&ctxl, g_ctxl);
    cudaGetSymbolAddress((void**)&Ph,   g_Ph);    cudaGetSymbolAddress((void**)&Pl,   g_Pl);
    cudaGetSymbolAddress((void**)&Wah,  g_Wah);   cudaGetSymbolAddress((void**)&Wal,  g_Wal);
    cudaGetSymbolAddress((void**)&Wth,  g_Wth);   cudaGetSymbolAddress((void**)&Wtl,  g_Wtl);
    cudaGetSymbolAddress((void**)&Wbh,  g_Wbh);   cudaGetSymbolAddress((void**)&Wbl,  g_Wbl);
    cudaGetSymbolAddress((void**)&AWh,  g_AWh);   cudaGetSymbolAddress((void**)&AWl,  g_AWl);
    cudaGetSymbolAddress((void**)&WIHh, g_WIHh);  cudaGetSymbolAddress((void**)&WIHl, g_WIHl);
    cudaGetSymbolAddress((void**)&WHHh, g_WHHh);  cudaGetSymbolAddress((void**)&WHHl, g_WHHl);

    float* out = (float*)d_out;
    const int HN = M_ATOM * DDIM;
    const bool direct = (out_size >= HN + BBATCH);
    const int gA = M_ATOM / 128;  // 256
    const int gW = M_ATOM / 8;    // warp-per-row grids (4096 blocks)

    const int SMEM = 2 * (2 * 128 * 72 + 2 * 64 * 72) * 2;   // 110592
    cudaFuncSetAttribute(gemm_bf_k<0,1,3>, cudaFuncAttributeMaxDynamicSharedMemorySize, SMEM);
    cudaFuncSetAttribute(gemm_bf_k<0,0,1>, cudaFuncAttributeMaxDynamicSharedMemorySize, SMEM);
    cudaFuncSetAttribute(gemm_bf_k<0,3,2>, cudaFuncAttributeMaxDynamicSharedMemorySize, SMEM);
    cudaFuncSetAttribute(gemm_gru_k,       cudaFuncAttributeMaxDynamicSharedMemorySize, SMEM);

    // launch 0: ALL conversions
    conv_all_k<<<(CONV_TOTAL + 255) / 256, 256>>>(
        atom_list, bond_list, atom_fc_w, nbr_fc_w, attend_w, mol_attend_w,
        gru_wih, gru_whh,
        A64h, A64l, B64h, B64l, Wah, Wal, Wth, Wtl, Wbh, Wbl,
        AWh, AWl, WIHh, WIHl, WHHh, WHHl);

    // ---- entry GEMMs ----
    gemm_bf_k<0,1,3><<<dim3(gA, 2), 256, SMEM>>>(A64h, A64l, Wah, Wal, atom_fc_b, nullptr,
                                                 p_h, hh, hl, 64, DDIM);
    gemm_bf_k<0,0,1><<<dim3(gA, 2), 256, SMEM>>>(A64h, A64l, Wth, Wtl, nullptr, nullptr,
                                                 p_atomT, nullptr, nullptr, 64, DDIM);
    gemm_bf_k<0,0,1><<<dim3(gA, 2), 256, SMEM>>>(B64h, B64l, Wbh, Wbl, nullptr, nullptr,
                                                 p_bondT, nullptr, nullptr, 64, DDIM);

    // ---- radius 0 ----
    attn0_k<<<gW, 256>>>(p_h, p_atomT, p_bondT, adl, bdl, nbr_fc_b,
                         align_w, align_b, Ph, Pl, p_sumw);
    gemm_bf_k<0,3,2><<<dim3(gA, 2), 256, SMEM>>>(Ph, Pl, AWh, AWl, attend_b, p_sumw,
                                                 nullptr, ctxh, ctxl, DDIM, DDIM);
    gemm_gru_k<<<dim3(gA, 6, 2), 256, SMEM>>>(ctxh, ctxl, hh, hl,
                                              WIHh, WIHl, WHHh, WHHl, p_gi, p_gh);
    gru_gate_k<<<(M_ATOM * 32 + 255) / 256, 256>>>(p_gi, p_gh, gru_bih, gru_bhh,
                                                   p_h, p_act, hh, hl, acth, actl, nullptr, M_ATOM);

    // ---- radii 1..R-1 ----
    for (int d = 1; d < NRAD; ++d) {
        dot2_k<<<gW, 256>>>(p_act, align_w + d * 2 * DDIM, align_w + d * 2 * DDIM + DDIM,
                            p_sc, p_sn);
        gemm_bf_k<0,0,1><<<dim3(gA, 2), 256, SMEM>>>(acth, actl, AWh + (size_t)d * 16384,
                                                     AWl + (size_t)d * 16384, nullptr, nullptr,
                                                     p_P, nullptr, nullptr, DDIM, DDIM);
        attn_k<<<gW, 256>>>(p_sc, p_sn, p_P, adl, align_b + d, attend_b + d * DDIM,
                            ctxh, ctxl);
        gemm_gru_k<<<dim3(gA, 6, 2), 256, SMEM>>>(ctxh, ctxl, hh, hl,
                                                  WIHh + (size_t)d * 49152, WIHl + (size_t)d * 49152,
                                                  WHHh + (size_t)d * 49152, WHHl + (size_t)d * 49152,
                                                  p_gi, p_gh);
        float* oh = (direct && d == NRAD - 1) ? out : nullptr;
        gru_gate_k<<<(M_ATOM * 32 + 255) / 256, 256>>>(p_gi, p_gh, gru_bih + d * 384,
                                                       gru_bhh + d * 384, p_h, p_act,
                                                       hh, hl, acth, actl, oh, M_ATOM);
    }

    // ---- molecule phase ----
    molsum_k<<<BBATCH, 128>>>(p_act, atom_mask, p_molf);
    gemm_bf_k<0,0,1><<<dim3(gA, 2), 256, SMEM>>>(acth, actl, AWh + 3 * 16384, AWl + 3 * 16384,
                                                 nullptr, nullptr, p_P, nullptr, nullptr,
                                                 DDIM, DDIM);
    dot128_k<<<gW, 256>>>(p_act, mol_align_w + DDIM, p_sn);
    float* pred_dst = direct ? (out + HN) : p_pred;
    mol_k<<<BBATCH, 128>>>(p_molf, atom_mask, p_sn, p_P, mol_align_w, mol_align_b, mol_attend_b,
                           mol_gru_wih, mol_gru_whh, mol_gru_bih, mol_gru_bhh,
                           out_w, out_b, p_molf, pred_dst);

    // ---- fallback output paths ----
    if (!direct) {
        if (out_size == BBATCH) {
            copy_k<<<1, 256>>>(p_pred, out, BBATCH);
        } else {
            int n = out_size < HN ? out_size : HN;
            copy_k<<<(n + 255) / 256, 256>>>(p_h, out, n);
        }
    }
    (void)in_sizes; (void)n_in;
}

// round 17
// speedup vs baseline: 1.3897x; 1.3897x over previous
#include <cuda_runtime.h>
#include <cuda_bf16.h>
#include <mma.h>
#include <math.h>
#include <stdint.h>

using namespace nvcuda;

#define BBATCH 256
#define LLEN   128
#define KNBR   6
#define FAD    39
#define FBD    10
#define DDIM   128
#define NRAD   3
#define NTS    2
#define NEGV   (-9e8f)

static const int M_ATOM = BBATCH * LLEN;          // 32768

// ---------------- scratch (device globals; no allocations) ----------------
__device__ __align__(256) float g_h    [32768 * 128];
__device__ __align__(256) float g_act  [32768 * 128];
__device__ __align__(256) float g_P    [32768 * 128];
__device__ __align__(256) float g_atomT[32768 * 128];
__device__ __align__(256) float g_bondT[32768 * 128];
__device__ __align__(256) float g_gi   [32768 * 384];
__device__ __align__(256) float g_gh   [32768 * 384];
__device__ __align__(256) float g_sc   [32768];
__device__ __align__(256) float g_sn   [32768];
__device__ __align__(256) float g_sumw [32768];
__device__ __align__(256) float g_molf [256 * 128];
__device__ __align__(256) float g_pred [256];
// bf16 hi/lo activations
__device__ __align__(256) __nv_bfloat16 g_A64h [32768 * 64];
__device__ __align__(256) __nv_bfloat16 g_A64l [32768 * 64];
__device__ __align__(256) __nv_bfloat16 g_B64h [32768 * 64];
__device__ __align__(256) __nv_bfloat16 g_B64l [32768 * 64];
__device__ __align__(256) __nv_bfloat16 g_hh   [32768 * 128];
__device__ __align__(256) __nv_bfloat16 g_hl   [32768 * 128];
__device__ __align__(256) __nv_bfloat16 g_acth [32768 * 128];
__device__ __align__(256) __nv_bfloat16 g_actl [32768 * 128];
__device__ __align__(256) __nv_bfloat16 g_ctxh [32768 * 128];
__device__ __align__(256) __nv_bfloat16 g_ctxl [32768 * 128];
__device__ __align__(256) __nv_bfloat16 g_Ph   [32768 * 128];
__device__ __align__(256) __nv_bfloat16 g_Pl   [32768 * 128];
// bf16 hi/lo weights
__device__ __align__(256) __nv_bfloat16 g_Wah [64 * 128];
__device__ __align__(256) __nv_bfloat16 g_Wal [64 * 128];
__device__ __align__(256) __nv_bfloat16 g_Wth [64 * 128];
__device__ __align__(256) __nv_bfloat16 g_Wtl [64 * 128];
__device__ __align__(256) __nv_bfloat16 g_Wbh [64 * 128];
__device__ __align__(256) __nv_bfloat16 g_Wbl [64 * 128];
__device__ __align__(256) __nv_bfloat16 g_AWh [4 * 128 * 128];
__device__ __align__(256) __nv_bfloat16 g_AWl [4 * 128 * 128];
__device__ __align__(256) __nv_bfloat16 g_WIHh[3 * 384 * 128];
__device__ __align__(256) __nv_bfloat16 g_WIHl[3 * 384 * 128];
__device__ __align__(256) __nv_bfloat16 g_WHHh[3 * 384 * 128];
__device__ __align__(256) __nv_bfloat16 g_WHHl[3 * 384 * 128];

// ---------------- helpers ----------------
__device__ __forceinline__ void f2bf_split(float x, __nv_bfloat16& hi, __nv_bfloat16& lo)
{
    hi = __float2bfloat16(x);
    lo = __float2bfloat16(x - __bfloat162float(hi));
}
__device__ __forceinline__ void f2bf_split2(float x, float y,
                                            __nv_bfloat162& hi, __nv_bfloat162& lo)
{
    __nv_bfloat16 hx = __float2bfloat16(x);
    __nv_bfloat16 hy = __float2bfloat16(y);
    hi = __nv_bfloat162(hx, hy);
    lo = __nv_bfloat162(__float2bfloat16(x - __bfloat162float(hx)),
                        __float2bfloat16(y - __bfloat162float(hy)));
}
__device__ __forceinline__ void store_split4(__nv_bfloat16* dh, __nv_bfloat16* dl,
                                             size_t off, float4 v)
{
    __nv_bfloat162 h0, l0, h1, l1;
    f2bf_split2(v.x, v.y, h0, l0);
    f2bf_split2(v.z, v.w, h1, l1);
    *(__nv_bfloat162*)(dh + off)     = h0;
    *(__nv_bfloat162*)(dh + off + 2) = h1;
    *(__nv_bfloat162*)(dl + off)     = l0;
    *(__nv_bfloat162*)(dl + off + 2) = l1;
}
__device__ __forceinline__ uint32_t smem_u32(const void* p)
{
    uint32_t a;
    asm("{ .reg .u64 t; cvta.to.shared.u64 t, %1; cvt.u32.u64 %0, t; }" : "=r"(a) : "l"(p));
    return a;
}
__device__ __forceinline__ void cp16(uint32_t dst, const void* src)
{
    asm volatile("cp.async.ca.shared.global [%0], [%1], 16;" :: "r"(dst), "l"(src));
}
__device__ __forceinline__ void cp_commit() { asm volatile("cp.async.commit_group;"); }
__device__ __forceinline__ void cp_wait1()  { asm volatile("cp.async.wait_group 1;"); }
__device__ __forceinline__ void cp_wait0()  { asm volatile("cp.async.wait_group 0;"); }

// ============== bf16x3 GEMM body, BK=64, cp.async 2-stage pipeline =========
template<int BL, int MODE, int OUT>
__device__ __forceinline__ void gemm_body(
    const __nv_bfloat16* __restrict__ Ah, const __nv_bfloat16* __restrict__ Al,
    const __nv_bfloat16* __restrict__ Bh, const __nv_bfloat16* __restrict__ Bl,
    const float* __restrict__ bias, const float* __restrict__ rowscale,
    float* __restrict__ C, __nv_bfloat16* __restrict__ Chi, __nv_bfloat16* __restrict__ Clo,
    int K, int N, char* dyn)
{
    constexpr int LDA = 72;
    constexpr int LDB = 72;
    constexpr int A_SZ = 128 * LDA;
    constexpr int B_SZ = 64 * LDB;
    constexpr int STG  = 2 * A_SZ + 2 * B_SZ;

    __nv_bfloat16* base = (__nv_bfloat16*)dyn;
    const uint32_t sbase = smem_u32(dyn);
    const int tid  = threadIdx.x;
    const int warp = tid >> 5;
    const int wm = warp >> 1, wn = warp & 1;
    const int m0 = blockIdx.x * 128, n0 = blockIdx.y * 64;

    auto issue = [&](int kt, int s) {
        const int k0 = kt << 6;
        const uint32_t su = sbase + (uint32_t)s * STG * 2;
#pragma unroll
        for (int t = 0; t < 4; ++t) {
            int i = tid + t * 256;
            int row = i >> 3, q = (i & 7) * 8;
            size_t goff = (size_t)(m0 + row) * K + k0 + q;
            cp16(su + (row * LDA + q) * 2,          Ah + goff);
            cp16(su + (A_SZ + row * LDA + q) * 2,   Al + goff);
        }
#pragma unroll
        for (int t = 0; t < 2; ++t) {
            int i = tid + t * 256;
            int r = i >> 3, q = (i & 7) * 8;
            size_t goff;
            if (BL == 0) goff = (size_t)(k0 + r) * N + n0 + q;
            else         goff = (size_t)(n0 + r) * K + k0 + q;
            cp16(su + (2 * A_SZ + r * LDB + q) * 2,        Bh + goff);
            cp16(su + (2 * A_SZ + B_SZ + r * LDB + q) * 2, Bl + goff);
        }
        cp_commit();
    };

    wmma::fragment<wmma::accumulator, 16, 16, 16, float> acc[2][2];
#pragma unroll
    for (int mi = 0; mi < 2; ++mi)
#pragma unroll
        for (int ni = 0; ni < 2; ++ni) wmma::fill_fragment(acc[mi][ni], 0.f);

    const int nk = K >> 6;
    issue(0, 0);
    for (int kt = 0; kt < nk; ++kt) {
        if (kt + 1 < nk) { issue(kt + 1, (kt + 1) & 1); cp_wait1(); }
        else             { cp_wait0(); }
        __syncthreads();
        const __nv_bfloat16* st  = base + (size_t)(kt & 1) * STG;
        const __nv_bfloat16* sAh = st;
        const __nv_bfloat16* sAl = st + A_SZ;
        const __nv_bfloat16* sBh = st + 2 * A_SZ;
        const __nv_bfloat16* sBl = sBh + B_SZ;
#pragma unroll
        for (int kc = 0; kc < 64; kc += 16) {
            wmma::fragment<wmma::matrix_a, 16, 16, 16, __nv_bfloat16, wmma::row_major> ah[2], al[2];
#pragma unroll
            for (int mi = 0; mi < 2; ++mi) {
                wmma::load_matrix_sync(ah[mi], sAh + (wm * 32 + mi * 16) * LDA + kc, LDA);
                wmma::load_matrix_sync(al[mi], sAl + (wm * 32 + mi * 16) * LDA + kc, LDA);
            }
            if (BL == 0) {
                wmma::fragment<wmma::matrix_b, 16, 16, 16, __nv_bfloat16, wmma::row_major> bh[2], bl[2];
#pragma unroll
                for (int ni = 0; ni < 2; ++ni) {
                    wmma::load_matrix_sync(bh[ni], sBh + kc * LDB + wn * 32 + ni * 16, LDB);
                    wmma::load_matrix_sync(bl[ni], sBl + kc * LDB + wn * 32 + ni * 16, LDB);
                }
#pragma unroll
                for (int mi = 0; mi < 2; ++mi)
#pragma unroll
                    for (int ni = 0; ni < 2; ++ni) {
                        wmma::mma_sync(acc[mi][ni], ah[mi], bl[ni], acc[mi][ni]);
                        wmma::mma_sync(acc[mi][ni], al[mi], bh[ni], acc[mi][ni]);
                        wmma::mma_sync(acc[mi][ni], ah[mi], bh[ni], acc[mi][ni]);
                    }
            } else {
                wmma::fragment<wmma::matrix_b, 16, 16, 16, __nv_bfloat16, wmma::col_major> bh[2], bl[2];
#pragma unroll
                for (int ni = 0; ni < 2; ++ni) {
                    wmma::load_matrix_sync(bh[ni], sBh + (wn * 32 + ni * 16) * LDB + kc, LDB);
                    wmma::load_matrix_sync(bl[ni], sBl + (wn * 32 + ni * 16) * LDB + kc, LDB);
                }
#pragma unroll
                for (int mi = 0; mi < 2; ++mi)
#pragma unroll
                    for (int ni = 0; ni < 2; ++ni) {
                        wmma::mma_sync(acc[mi][ni], ah[mi], bl[ni], acc[mi][ni]);
                        wmma::mma_sync(acc[mi][ni], al[mi], bh[ni], acc[mi][ni]);
                        wmma::mma_sync(acc[mi][ni], ah[mi], bh[ni], acc[mi][ni]);
                    }
            }
        }
        __syncthreads();
    }
    float* Cs = (float*)dyn;
#pragma unroll
    for (int mi = 0; mi < 2; ++mi)
#pragma unroll
        for (int ni = 0; ni < 2; ++ni)
            wmma::store_matrix_sync(Cs + (wm * 32 + mi * 16) * 72 + (wn * 32 + ni * 16),
                                    acc[mi][ni], 72, wmma::mem_row_major);
    __syncthreads();
#pragma unroll
    for (int t = 0; t < 8; ++t) {
        int i = tid + t * 256;
        int row = i >> 4, c4 = i & 15;
        float4 v = *(float4*)(Cs + row * 72 + c4 * 4);
        int n = n0 + c4 * 4;
        if (MODE == 1) {
            v.x += bias[n];     v.y += bias[n + 1];  v.z += bias[n + 2];  v.w += bias[n + 3];
            v.x = v.x > 0.f ? v.x : 0.01f * v.x;
            v.y = v.y > 0.f ? v.y : 0.01f * v.y;
            v.z = v.z > 0.f ? v.z : 0.01f * v.z;
            v.w = v.w > 0.f ? v.w : 0.01f * v.w;
        } else if (MODE == 3) {
            float rs = rowscale[m0 + row];
            v.x += rs * bias[n];     v.y += rs * bias[n + 1];
            v.z += rs * bias[n + 2]; v.w += rs * bias[n + 3];
            v.x = v.x > 0.f ? v.x : expm1f(v.x);
            v.y = v.y > 0.f ? v.y : expm1f(v.y);
            v.z = v.z > 0.f ? v.z : expm1f(v.z);
            v.w = v.w > 0.f ? v.w : expm1f(v.w);
        }
        size_t off = (size_t)(m0 + row) * N + n;
        if (OUT & 1) *(float4*)(C + off) = v;
        if (OUT & 2) store_split4(Chi, Clo, off, v);
    }
}

template<int BL, int MODE, int OUT>
__global__ void __launch_bounds__(256) gemm_bf_k(
    const __nv_bfloat16* __restrict__ Ah, const __nv_bfloat16* __restrict__ Al,
    const __nv_bfloat16* __restrict__ Bh, const __nv_bfloat16* __restrict__ Bl,
    const float* __restrict__ bias, const float* __restrict__ rowscale,
    float* __restrict__ C, __nv_bfloat16* __restrict__ Chi, __nv_bfloat16* __restrict__ Clo,
    int K, int N)
{
    extern __shared__ __align__(16) char dyn[];
    gemm_body<BL, MODE, OUT>(Ah, Al, Bh, Bl, bias, rowscale, C, Chi, Clo, K, N, dyn);
}

// merged entry GEMM: z=0 atom_fc (lrelu+bias, f32+bf16 out), z=1 atomT, z=2 bondT
__global__ void __launch_bounds__(256) gemm_entry3_k(
    const __nv_bfloat16* __restrict__ A64h, const __nv_bfloat16* __restrict__ A64l,
    const __nv_bfloat16* __restrict__ B64h, const __nv_bfloat16* __restrict__ B64l,
    const __nv_bfloat16* __restrict__ Wah,  const __nv_bfloat16* __restrict__ Wal,
    const __nv_bfloat16* __restrict__ Wth,  const __nv_bfloat16* __restrict__ Wtl,
    const __nv_bfloat16* __restrict__ Wbh,  const __nv_bfloat16* __restrict__ Wbl,
    const float* __restrict__ atom_fc_b,
    float* __restrict__ h, __nv_bfloat16* __restrict__ hh, __nv_bfloat16* __restrict__ hl,
    float* __restrict__ atomT, float* __restrict__ bondT)
{
    extern __shared__ __align__(16) char dyn[];
    if (blockIdx.z == 0)
        gemm_body<0, 1, 3>(A64h, A64l, Wah, Wal, atom_fc_b, nullptr,
                           h, hh, hl, 64, DDIM, dyn);
    else if (blockIdx.z == 1)
        gemm_body<0, 0, 1>(A64h, A64l, Wth, Wtl, nullptr, nullptr,
                           atomT, nullptr, nullptr, 64, DDIM, dyn);
    else
        gemm_body<0, 0, 1>(B64h, B64l, Wbh, Wbl, nullptr, nullptr,
                           bondT, nullptr, nullptr, 64, DDIM, dyn);
}

// merged GRU GEMM: z=0 -> gi = ctx@WIH^T, z=1 -> gh = h@WHH^T
__global__ void __launch_bounds__(256) gemm_gru_k(
    const __nv_bfloat16* __restrict__ ctxh, const __nv_bfloat16* __restrict__ ctxl,
    const __nv_bfloat16* __restrict__ hh,   const __nv_bfloat16* __restrict__ hl,
    const __nv_bfloat16* __restrict__ WIHh, const __nv_bfloat16* __restrict__ WIHl,
    const __nv_bfloat16* __restrict__ WHHh, const __nv_bfloat16* __restrict__ WHHl,
    float* __restrict__ gi, float* __restrict__ gh)
{
    extern __shared__ __align__(16) char dyn[];
    if (blockIdx.z == 0)
        gemm_body<1, 0, 1>(ctxh, ctxl, WIHh, WIHl, nullptr, nullptr,
                           gi, nullptr, nullptr, DDIM, 384, dyn);
    else
        gemm_body<1, 0, 1>(hh, hl, WHHh, WHHl, nullptr, nullptr,
                           gh, nullptr, nullptr, DDIM, 384, dyn);
}

// ---------------- block reductions ----------------
__device__ __forceinline__ float blk_sum(float v, float* red, int j)
{
#pragma unroll
    for (int o = 16; o > 0; o >>= 1) v += __shfl_down_sync(0xffffffffu, v, o);
    if ((j & 31) == 0) red[j >> 5] = v;
    __syncthreads();
    v = red[0] + red[1] + red[2] + red[3];
    __syncthreads();
    return v;
}
__device__ __forceinline__ float blk_max(float v, float* red, int j)
{
#pragma unroll
    for (int o = 16; o > 0; o >>= 1) v = fmaxf(v, __shfl_down_sync(0xffffffffu, v, o));
    if ((j & 31) == 0) red[j >> 5] = v;
    __syncthreads();
    v = fmaxf(fmaxf(red[0], red[1]), fmaxf(red[2], red[3]));
    __syncthreads();
    return v;
}

// ============== ONE merged conversion kernel ====
#define N_S0 2097152
#define N_S1 2097152
#define N_S2 8192
#define N_S3 8192
#define N_S4 8192
#define N_S5 65536
#define N_S6 147456
#define CONV_TOTAL (N_S0 + N_S1 + N_S2 + N_S3 + N_S4 + N_S5 + 2 * N_S6)

__global__ void conv_all_k(
    const float* __restrict__ atom, const float* __restrict__ bond,
    const float* __restrict__ atom_fc_w, const float* __restrict__ nbr_fc_w,
    const float* __restrict__ attend_w, const float* __restrict__ mol_attend_w,
    const float* __restrict__ gru_wih, const float* __restrict__ gru_whh,
    __nv_bfloat16* __restrict__ A64h, __nv_bfloat16* __restrict__ A64l,
    __nv_bfloat16* __restrict__ B64h, __nv_bfloat16* __restrict__ B64l,
    __nv_bfloat16* __restrict__ Wah,  __nv_bfloat16* __restrict__ Wal,
    __nv_bfloat16* __restrict__ Wth,  __nv_bfloat16* __restrict__ Wtl,
    __nv_bfloat16* __restrict__ Wbh,  __nv_bfloat16* __restrict__ Wbl,
    __nv_bfloat16* __restrict__ AWh,  __nv_bfloat16* __restrict__ AWl,
    __nv_bfloat16* __restrict__ WIHh, __nv_bfloat16* __restrict__ WIHl,
    __nv_bfloat16* __restrict__ WHHh, __nv_bfloat16* __restrict__ WHHl)
{
    int i = blockIdx.x * blockDim.x + threadIdx.x;
    if (i >= CONV_TOTAL) return;
    float v; __nv_bfloat16 h, l;
    if (i < N_S0) {
        int r = i >> 6, t = i & 63;
        v = (t < FAD) ? atom[(size_t)r * FAD + t] : 0.f;
        f2bf_split(v, h, l); A64h[i] = h; A64l[i] = l; return;
    }
    i -= N_S0;
    if (i < N_S1) {
        int r = i >> 6, t = i & 63;
        v = (t < FBD) ? bond[(size_t)r * FBD + t] : 0.f;
        f2bf_split(v, h, l); B64h[i] = h; B64l[i] = l; return;
    }
    i -= N_S1;
    if (i < N_S2) {
        int r = i >> 7;
        v = (r < FAD) ? atom_fc_w[i] : 0.f;
        f2bf_split(v, h, l); Wah[i] = h; Wal[i] = l; return;
    }
    i -= N_S2;
    if (i < N_S3) {
        int r = i >> 7;
        v = (r < FAD) ? nbr_fc_w[i] : 0.f;
        f2bf_split(v, h, l); Wth[i] = h; Wtl[i] = l; return;
    }
    i -= N_S3;
    if (i < N_S4) {
        int r = i >> 7, j = i & 127;
        v = (r < FBD) ? nbr_fc_w[(FAD + r) * 128 + j] : 0.f;
        f2bf_split(v, h, l); Wbh[i] = h; Wbl[i] = l; return;
    }
    i -= N_S4;
    if (i < N_S5) {
        v = (i < 49152) ? attend_w[i] : mol_attend_w[i - 49152];
        f2bf_split(v, h, l); AWh[i] = h; AWl[i] = l; return;
    }
    i -= N_S5;
    if (i < N_S6) {
        v = gru_wih[i];
        f2bf_split(v, h, l); WIHh[i] = h; WIHl[i] = l; return;
    }
    i -= N_S6;
    v = gru_whh[i];
    f2bf_split(v, h, l); WHHh[i] = h; WHHl[i] = l;
}

// ---------------- fused d=0 attention (R15 proven version) ----------------
__global__ void attn0_k(const float* __restrict__ h, const float* __restrict__ atomT,
                        const float* __restrict__ bondT, const int* __restrict__ adl,
                        const int* __restrict__ bdl, const float* __restrict__ nbias,
                        const float* __restrict__ aw, const float* __restrict__ ab,
                        __nv_bfloat16* __restrict__ ph, __nv_bfloat16* __restrict__ pl,
                        float* __restrict__ sumw)
{
    int bl = blockIdx.x, j = threadIdx.x;
    int bbase = (bl >> 7) << 7;
    __shared__ float red[4];
    const int base = bl * KNBR;
    float sc = blk_sum(h[(size_t)bl * DDIM + j] * aw[j], red, j);
    float aw2 = aw[DDIM + j];
    float ab0 = ab[0];
    float nb  = nbias[j];
    float v[KNBR], s[KNBR], msk[KNBR];
#pragma unroll
    for (int k = 0; k < KNBR; ++k) {
        int ai = adl[base + k], bi = bdl[base + k];
        float x = atomT[(size_t)(bbase + ai) * DDIM + j]
                + bondT[(size_t)(bbase + bi) * DDIM + j] + nb;
        v[k] = x > 0.f ? x : 0.01f * x;
        msk[k] = (ai == LLEN - 1) ? 0.f : 1.f;
    }
#pragma unroll
    for (int k = 0; k < KNBR; ++k) {
        float d = blk_sum(v[k] * aw2, red, j);
        float sco = sc + d + ab0;
        sco = sco > 0.f ? sco : 0.01f * sco;
        if (msk[k] == 0.f) sco += NEGV;
        s[k] = sco;
    }
    float mx = -1e30f;
#pragma unroll
    for (int k = 0; k < KNBR; ++k) mx = fmaxf(mx, s[k]);
    float ss = 0.f;
#pragma unroll
    for (int k = 0; k < KNBR; ++k) { s[k] = expf(s[k] - mx); ss += s[k]; }
    float acc = 0.f, sw = 0.f;
#pragma unroll
    for (int k = 0; k < KNBR; ++k) {
        float w = s[k] / ss * msk[k];
        acc = fmaf(w, v[k], acc);
        sw += w;
    }
    __nv_bfloat16 hh_, ll_; f2bf_split(acc, hh_, ll_);
    ph[(size_t)bl * DDIM + j] = hh_;
    pl[(size_t)bl * DDIM + j] = ll_;
    if (j == 0) sumw[bl] = sw;
}

// ---------------- warp-per-row dot kernels (R15 proven) ----------------
__global__ void __launch_bounds__(256) dot2_k(
    const float* __restrict__ X, const float* __restrict__ w1,
    const float* __restrict__ w2, float* __restrict__ o1, float* __restrict__ o2)
{
    int warp = (blockIdx.x << 3) + (threadIdx.x >> 5);
    int lane = threadIdx.x & 31;
    const float4 x  = *(const float4*)(X + (size_t)warp * DDIM + lane * 4);
    const float4 a4 = *(const float4*)(w1 + lane * 4);
    const float4 b4 = *(const float4*)(w2 + lane * 4);
    float a = x.x * a4.x + x.y * a4.y + x.z * a4.z + x.w * a4.w;
    float b = x.x * b4.x + x.y * b4.y + x.z * b4.z + x.w * b4.w;
#pragma unroll
    for (int o = 16; o > 0; o >>= 1) {
        a += __shfl_down_sync(0xffffffffu, a, o);
        b += __shfl_down_sync(0xffffffffu, b, o);
    }
    if (lane == 0) { o1[warp] = a; o2[warp] = b; }
}
__global__ void __launch_bounds__(256) dot128_k(
    const float* __restrict__ X, const float* __restrict__ v, float* __restrict__ out)
{
    int warp = (blockIdx.x << 3) + (threadIdx.x >> 5);
    int lane = threadIdx.x & 31;
    const float4 x  = *(const float4*)(X + (size_t)warp * DDIM + lane * 4);
    const float4 a4 = *(const float4*)(v + lane * 4);
    float a = x.x * a4.x + x.y * a4.y + x.z * a4.z + x.w * a4.w;
#pragma unroll
    for (int o = 16; o > 0; o >>= 1) a += __shfl_down_sync(0xffffffffu, a, o);
    if (lane == 0) out[warp] = a;
}

// ---------------- d>=1 attention (R15 proven version) ----------------
__global__ void attn_k(const float* __restrict__ sc, const float* __restrict__ sn,
                       const float* __restrict__ P, const int* __restrict__ adl,
                       const float* __restrict__ abp, const float* __restrict__ tb,
                       __nv_bfloat16* __restrict__ ctxh, __nv_bfloat16* __restrict__ ctxl)
{
    int bl = blockIdx.x;
    int b  = bl >> 7;
    int j  = threadIdx.x;
    __shared__ float ws[KNBR];
    __shared__ float swsh;
    __shared__ int   rowidx[KNBR];
    if (j == 0) {
        float ab = abp[0];
        float s[KNBR], msk[KNBR];
        float mx = -1e30f;
#pragma unroll
        for (int k = 0; k < KNBR; ++k) {
            int id = adl[bl * KNBR + k];
            int src = b * LLEN + id;
            rowidx[k] = src;
            float sco = sc[bl] + sn[src] + ab;
            sco = sco > 0.f ? sco : 0.01f * sco;
            bool pad = (id == LLEN - 1);
            if (pad) sco += NEGV;
            msk[k] = pad ? 0.f : 1.f;
            s[k] = sco;
            mx = fmaxf(mx, sco);
        }
        float sum = 0.f;
#pragma unroll
        for (int k = 0; k < KNBR; ++k) { s[k] = expf(s[k] - mx); sum += s[k]; }
        float sw = 0.f;
#pragma unroll
        for (int k = 0; k < KNBR; ++k) { ws[k] = s[k] / sum * msk[k]; sw += ws[k]; }
        swsh = sw;
    }
    __syncthreads();
    float c = 0.f;
#pragma unroll
    for (int k = 0; k < KNBR; ++k)
        c = fmaf(ws[k], P[(size_t)rowidx[k] * DDIM + j], c);
    c += swsh * tb[j];
    c = c > 0.f ? c : expm1f(c);
    __nv_bfloat16 hh_, ll_; f2bf_split(c, hh_, ll_);
    ctxh[(size_t)bl * DDIM + j] = hh_;
    ctxl[(size_t)bl * DDIM + j] = ll_;
}

// ---------------- GRU gate fusion, float4-vectorized ----------------
__global__ void gru_gate_k(const float* __restrict__ gi, const float* __restrict__ gh,
                           const float* __restrict__ bih, const float* __restrict__ bhh,
                           float* __restrict__ h, float* __restrict__ act,
                           __nv_bfloat16* __restrict__ hh_o, __nv_bfloat16* __restrict__ hl_o,
                           __nv_bfloat16* __restrict__ ah_o, __nv_bfloat16* __restrict__ al_o,
                           float* __restrict__ out_h, int M)
{
    int g4 = blockIdx.x * blockDim.x + threadIdx.x;
    if (g4 >= M * 32) return;
    int m = g4 >> 5, j = (g4 & 31) * 4;
    size_t gbase = (size_t)m * 384 + j;
    size_t hbase = (size_t)m * 128 + j;
    float4 ir = *(const float4*)(gi + gbase);
    float4 iz = *(const float4*)(gi + gbase + 128);
    float4 in = *(const float4*)(gi + gbase + 256);
    float4 hr = *(const float4*)(gh + gbase);
    float4 hz = *(const float4*)(gh + gbase + 128);
    float4 hn = *(const float4*)(gh + gbase + 256);
    float4 b0 = *(const float4*)(bih + j);
    float4 b1 = *(const float4*)(bih + 128 + j);
    float4 b2 = *(const float4*)(bih + 256 + j);
    float4 c0 = *(const float4*)(bhh + j);
    float4 c1 = *(const float4*)(bhh + 128 + j);
    float4 c2 = *(const float4*)(bhh + 256 + j);
    float4 hv = *(const float4*)(h + hbase);
    float4 hnew, av;
#pragma unroll
    for (int e = 0; e < 4; ++e) {
        float irv = (&ir.x)[e] + (&b0.x)[e];
        float izv = (&iz.x)[e] + (&b1.x)[e];
        float inv = (&in.x)[e] + (&b2.x)[e];
        float hrv = (&hr.x)[e] + (&c0.x)[e];
        float hzv = (&hz.x)[e] + (&c1.x)[e];
        float hnv = (&hn.x)[e] + (&c2.x)[e];
        float r = 1.f / (1.f + expf(-(irv + hrv)));
        float z = 1.f / (1.f + expf(-(izv + hzv)));
        float n = tanhf(inv + r * hnv);
        float ho = (1.f - z) * n + z * (&hv.x)[e];
        (&hnew.x)[e] = ho;
        (&av.x)[e] = ho > 0.f ? ho : 0.f;
    }
    *(float4*)(h + hbase)   = hnew;
    *(float4*)(act + hbase) = av;
    store_split4(hh_o, hl_o, hbase, hnew);
    store_split4(ah_o, al_o, hbase, av);
    if (out_h) *(float4*)(out_h + hbase) = hnew;
}

// ---------------- masked sum over atoms ----------------
__global__ void molsum_k(const float* __restrict__ act, const float* __restrict__ mask,
                         float* __restrict__ molf)
{
    int b = blockIdx.x, j = threadIdx.x;
    float s = 0.f;
    for (int l = 0; l < LLEN; ++l)
        s = fmaf(act[((size_t)b * LLEN + l) * DDIM + j], mask[b * LLEN + l], s);
    molf[b * DDIM + j] = s;
}

// ---------------- per-molecule mol-attention + GRU ----------------
__global__ void mol_k(const float* __restrict__ molf_in, const float* __restrict__ mask,
                      const float* __restrict__ snm, const float* __restrict__ Pm,
                      const float* __restrict__ maw, const float* __restrict__ mab,
                      const float* __restrict__ matt_b,
                      const float* __restrict__ wih, const float* __restrict__ whh,
                      const float* __restrict__ bih, const float* __restrict__ bhh,
                      const float* __restrict__ outw, const float* __restrict__ outb,
                      float* __restrict__ molf_out, float* __restrict__ pred)
{
    int b = blockIdx.x;
    int j = threadIdx.x;
    __shared__ float smolf[DDIM];
    __shared__ float w[LLEN];
    __shared__ float sctx[DDIM];
    __shared__ float red[4];
    smolf[j] = molf_in[b * DDIM + j];
    float mymask = mask[b * LLEN + j];
    float mysnm  = snm[b * LLEN + j];
    float mabv   = mab[0];
    float mybias = matt_b[j];

    for (int t = 0; t < NTS; ++t) {
        __syncthreads();
        float amj = fmaxf(smolf[j], 0.f);
        float scv = blk_sum(amj * maw[j], red, j);
        float sco = scv + mysnm + mabv;
        sco = sco > 0.f ? sco : 0.01f * sco;
        if (mymask == 0.f) sco += NEGV;
        float mx = blk_max(sco, red, j);
        float ev = expf(sco - mx);
        float ss = blk_sum(ev, red, j);
        float wj = ev / ss * mymask;
        w[j] = wj;
        float sumw = blk_sum(wj, red, j);
        __syncthreads();
        float c = 0.f;
#pragma unroll 4
        for (int l = 0; l < LLEN; ++l)
            c = fmaf(w[l], Pm[((size_t)b * LLEN + l) * DDIM + j], c);
        c += sumw * mybias;
        c = c > 0.f ? c : expm1f(c);
        sctx[j] = c;
        __syncthreads();
        float gi0 = bih[j], gi1 = bih[DDIM + j], gi2 = bih[2 * DDIM + j];
        float gh0 = bhh[j], gh1 = bhh[DDIM + j], gh2 = bhh[2 * DDIM + j];
        const float* wi0 = wih + (size_t)j * DDIM;
        const float* wi1 = wih + (size_t)(DDIM + j) * DDIM;
        const float* wi2 = wih + (size_t)(2 * DDIM + j) * DDIM;
        const float* wh0 = whh + (size_t)j * DDIM;
        const float* wh1 = whh + (size_t)(DDIM + j) * DDIM;
        const float* wh2 = whh + (size_t)(2 * DDIM + j) * DDIM;
#pragma unroll 4
        for (int k = 0; k < DDIM; ++k) {
            float ck = sctx[k], hk = smolf[k];
            gi0 = fmaf(ck, wi0[k], gi0);
            gi1 = fmaf(ck, wi1[k], gi1);
            gi2 = fmaf(ck, wi2[k], gi2);
            gh0 = fmaf(hk, wh0[k], gh0);
            gh1 = fmaf(hk, wh1[k], gh1);
            gh2 = fmaf(hk, wh2[k], gh2);
        }
        float r = 1.f / (1.f + expf(-(gi0 + gh0)));
        float z = 1.f / (1.f + expf(-(gi1 + gh1)));
        float n = tanhf(gi2 + r * gh2);
        float hnew = (1.f - z) * n + z * smolf[j];
        __syncthreads();
        smolf[j] = hnew;
    }
    __syncthreads();
    molf_out[b * DDIM + j] = smolf[j];
    float tot = blk_sum(smolf[j] * outw[j], red, j);
    if (j == 0) pred[b] = tot + outb[0];
}

__global__ void copy_k(const float* __restrict__ src, float* __restrict__ dst, int n)
{
    int i = blockIdx.x * blockDim.x + threadIdx.x;
    if (i < n) dst[i] = src[i];
}

// ---------------- launcher ----------------
extern "C" void kernel_launch(void* const* d_in, const int* in_sizes, int n_in,
                              void* d_out, int out_size)
{
    const float* atom_list    = (const float*)d_in[0];
    const float* bond_list    = (const float*)d_in[1];
    const float* atom_mask    = (const float*)d_in[2];
    const float* atom_fc_w    = (const float*)d_in[3];
    const float* atom_fc_b    = (const float*)d_in[4];
    const float* nbr_fc_w     = (const float*)d_in[5];
    const float* nbr_fc_b     = (const float*)d_in[6];
    const float* align_w      = (const float*)d_in[7];
    const float* align_b      = (const float*)d_in[8];
    const float* attend_w     = (const float*)d_in[9];
    const float* attend_b     = (const float*)d_in[10];
    const float* gru_wih      = (const float*)d_in[11];
    const float* gru_whh      = (const float*)d_in[12];
    const float* gru_bih      = (const float*)d_in[13];
    const float* gru_bhh      = (const float*)d_in[14];
    const float* mol_align_w  = (const float*)d_in[15];
    const float* mol_align_b  = (const float*)d_in[16];
    const float* mol_attend_w = (const float*)d_in[17];
    const float* mol_attend_b = (const float*)d_in[18];
    const float* mol_gru_wih  = (const float*)d_in[19];
    const float* mol_gru_whh  = (const float*)d_in[20];
    const float* mol_gru_bih  = (const float*)d_in[21];
    const float* mol_gru_bhh  = (const float*)d_in[22];
    const float* out_w        = (const float*)d_in[23];
    const float* out_b        = (const float*)d_in[24];
    const int*   adl          = (const int*)d_in[25];
    const int*   bdl          = (const int*)d_in[26];

    float *p_h, *p_act, *p_P, *p_atomT, *p_bondT, *p_gi, *p_gh,
          *p_sc, *p_sn, *p_sumw, *p_molf, *p_pred;
    __nv_bfloat16 *A64h, *A64l, *B64h, *B64l, *hh, *hl, *acth, *actl,
                  *ctxh, *ctxl, *Ph, *Pl, *Wah, *Wal, *Wth, *Wtl, *Wbh, *Wbl,
                  *AWh, *AWl, *WIHh, *WIHl, *WHHh, *WHHl;
    cudaGetSymbolAddress((void**)&p_h,     g_h);
    cudaGetSymbolAddress((void**)&p_act,   g_act);
    cudaGetSymbolAddress((void**)&p_P,     g_P);
    cudaGetSymbolAddress((void**)&p_atomT, g_atomT);
    cudaGetSymbolAddress((void**)&p_bondT, g_bondT);
    cudaGetSymbolAddress((void**)&p_gi,    g_gi);
    cudaGetSymbolAddress((void**)&p_gh,    g_gh);
    cudaGetSymbolAddress((void**)&p_sc,    g_sc);
    cudaGetSymbolAddress((void**)&p_sn,    g_sn);
    cudaGetSymbolAddress((void**)&p_sumw,  g_sumw);
    cudaGetSymbolAddress((void**)&p_molf,  g_molf);
    cudaGetSymbolAddress((void**)&p_pred,  g_pred);
    cudaGetSymbolAddress((void**)&A64h, g_A64h);  cudaGetSymbolAddress((void**)&A64l, g_A64l);
    cudaGetSymbolAddress((void**)&B64h, g_B64h);  cudaGetSymbolAddress((void**)&B64l, g_B64l);
    cudaGetSymbolAddress((void**)&hh,   g_hh);    cudaGetSymbolAddress((void**)&hl,   g_hl);
    cudaGetSymbolAddress((void**)&acth, g_acth);  cudaGetSymbolAddress((void**)&actl, g_actl);
    cudaGetSymbolAddress((void**)&ctxh, g_ctxh);  cudaGetSymbolAddress((void**)&ctxl, g_ctxl);
    cudaGetSymbolAddress((void**)&Ph,   g_Ph);    cudaGetSymbolAddress((void**)&Pl,   g_Pl);
    cudaGetSymbolAddress((void**)&Wah,  g_Wah);   cudaGetSymbolAddress((void**)&Wal,  g_Wal);
    cudaGetSymbolAddress((void**)&Wth,  g_Wth);   cudaGetSymbolAddress((void**)&Wtl,  g_Wtl);
    cudaGetSymbolAddress((void**)&Wbh,  g_Wbh);   cudaGetSymbolAddress((void**)&Wbl,  g_Wbl);
    cudaGetSymbolAddress((void**)&AWh,  g_AWh);   cudaGetSymbolAddress((void**)&AWl,  g_AWl);
    cudaGetSymbolAddress((void**)&WIHh, g_WIHh);  cudaGetSymbolAddress((void**)&WIHl, g_WIHl);
    cudaGetSymbolAddress((void**)&WHHh, g_WHHh);  cudaGetSymbolAddress((void**)&WHHl, g_WHHl);

    float* out = (float*)d_out;
    const int HN = M_ATOM * DDIM;
    const bool direct = (out_size >= HN + BBATCH);
    const int gA = M_ATOM / 128;  // 256
    const int gW = M_ATOM / 8;    // warp-per-row grids (4096 blocks)

    const int SMEM = 2 * (2 * 128 * 72 + 2 * 64 * 72) * 2;   // 110592
    cudaFuncSetAttribute(gemm_bf_k<0,0,1>, cudaFuncAttributeMaxDynamicSharedMemorySize, SMEM);
    cudaFuncSetAttribute(gemm_bf_k<0,3,2>, cudaFuncAttributeMaxDynamicSharedMemorySize, SMEM);
    cudaFuncSetAttribute(gemm_entry3_k,    cudaFuncAttributeMaxDynamicSharedMemorySize, SMEM);
    cudaFuncSetAttribute(gemm_gru_k,       cudaFuncAttributeMaxDynamicSharedMemorySize, SMEM);

    // launch 0: ALL conversions
    conv_all_k<<<(CONV_TOTAL + 255) / 256, 256>>>(
        atom_list, bond_list, atom_fc_w, nbr_fc_w, attend_w, mol_attend_w,
        gru_wih, gru_whh,
        A64h, A64l, B64h, B64l, Wah, Wal, Wth, Wtl, Wbh, Wbl,
        AWh, AWl, WIHh, WIHl, WHHh, WHHl);

    // launch 1: ALL three entry GEMMs (z-dispatched)
    gemm_entry3_k<<<dim3(gA, 2, 3), 256, SMEM>>>(
        A64h, A64l, B64h, B64l, Wah, Wal, Wth, Wtl, Wbh, Wbl,
        atom_fc_b, p_h, hh, hl, p_atomT, p_bondT);

    // ---- radius 0 ----
    attn0_k<<<M_ATOM, 128>>>(p_h, p_atomT, p_bondT, adl, bdl, nbr_fc_b,
                             align_w, align_b, Ph, Pl, p_sumw);
    gemm_bf_k<0,3,2><<<dim3(gA, 2), 256, SMEM>>>(Ph, Pl, AWh, AWl, attend_b, p_sumw,
                                                 nullptr, ctxh, ctxl, DDIM, DDIM);
    gemm_gru_k<<<dim3(gA, 6, 2), 256, SMEM>>>(ctxh, ctxl, hh, hl,
                                              WIHh, WIHl, WHHh, WHHl, p_gi, p_gh);
    gru_gate_k<<<(M_ATOM * 32 + 255) / 256, 256>>>(p_gi, p_gh, gru_bih, gru_bhh,
                                                   p_h, p_act, hh, hl, acth, actl, nullptr, M_ATOM);

    // ---- radii 1..R-1 ----
    for (int d = 1; d < NRAD; ++d) {
        dot2_k<<<gW, 256>>>(p_act, align_w + d * 2 * DDIM, align_w + d * 2 * DDIM + DDIM,
                            p_sc, p_sn);
        gemm_bf_k<0,0,1><<<dim3(gA, 2), 256, SMEM>>>(acth, actl, AWh + (size_t)d * 16384,
                                                     AWl + (size_t)d * 16384, nullptr, nullptr,
                                                     p_P, nullptr, nullptr, DDIM, DDIM);
        attn_k<<<M_ATOM, 128>>>(p_sc, p_sn, p_P, adl, align_b + d, attend_b + d * DDIM,
                                ctxh, ctxl);
        gemm_gru_k<<<dim3(gA, 6, 2), 256, SMEM>>>(ctxh, ctxl, hh, hl,
                                                  WIHh + (size_t)d * 49152, WIHl + (size_t)d * 49152,
                                                  WHHh + (size_t)d * 49152, WHHl + (size_t)d * 49152,
                                                  p_gi, p_gh);
        float* oh = (direct && d == NRAD - 1) ? out : nullptr;
        gru_gate_k<<<(M_ATOM * 32 + 255) / 256, 256>>>(p_gi, p_gh, gru_bih + d * 384,
                                                       gru_bhh + d * 384, p_h, p_act,
                                                       hh, hl, acth, actl, oh, M_ATOM);
    }

    // ---- molecule phase ----
    molsum_k<<<BBATCH, 128>>>(p_act, atom_mask, p_molf);
    gemm_bf_k<0,0,1><<<dim3(gA, 2), 256, SMEM>>>(acth, actl, AWh + 3 * 16384, AWl + 3 * 16384,
                                                 nullptr, nullptr, p_P, nullptr, nullptr,
                                                 DDIM, DDIM);
    dot128_k<<<gW, 256>>>(p_act, mol_align_w + DDIM, p_sn);
    float* pred_dst = direct ? (out + HN) : p_pred;
    mol_k<<<BBATCH, 128>>>(p_molf, atom_mask, p_sn, p_P, mol_align_w, mol_align_b, mol_attend_b,
                           mol_gru_wih, mol_gru_whh, mol_gru_bih, mol_gru_bhh,
                           out_w, out_b, p_molf, pred_dst);

    // ---- fallback output paths ----
    if (!direct) {
        if (out_size == BBATCH) {
            copy_k<<<1, 256>>>(p_pred, out, BBATCH);
        } else {
            int n = out_size < HN ? out_size : HN;
            copy_k<<<(n + 255) / 256, 256>>>(p_h, out, n);
        }
    }
    (void)in_sizes; (void)n_in;
}